// round 8
// baseline (speedup 1.0000x reference)
#include <cuda_runtime.h>
#include <cstdint>

#define N_ATOMS 500000
#define FDIM 128
#define TM 64
#define TN 128
#define TOTAL_TILES 7817

#define AS_S 132            // As row stride (words)
#define BS_S 136            // Bs row stride (words)
#define AS_WORDS (TM * AS_S)
#define BS_WORDS (32 * BS_S)
#define SMEM_BYTES ((AS_WORDS + 2 * BS_WORDS) * 4)   // 68608

__device__ __constant__ int d_OFFS[12] =
    {0, 10000, 110000, 260000, 410000, 490000, 495000, 497000, 498000, 499000, 499500, 500000};
__device__ __constant__ int d_TCUM[12] =
    {0, 157, 1720, 4064, 6408, 7658, 7737, 7769, 7785, 7801, 7809, 7817};

__device__ int g_idx64;
__device__ uint32_t g_wtf32[21 * FDIM * TN];

__device__ __forceinline__ uint32_t f2tf32(float x) {
    uint32_t y;
    asm("cvt.rna.tf32.f32 %0, %1;" : "=r"(y) : "f"(x));
    return y;
}

__device__ __forceinline__ void mma_tf32(float* c, const uint32_t* a, const uint32_t* b) {
    asm volatile(
        "mma.sync.aligned.m16n8k8.row.col.f32.tf32.tf32.f32 "
        "{%0,%1,%2,%3}, {%4,%5,%6,%7}, {%8,%9}, {%0,%1,%2,%3};\n"
        : "+f"(c[0]), "+f"(c[1]), "+f"(c[2]), "+f"(c[3])
        : "r"(a[0]), "r"(a[1]), "r"(a[2]), "r"(a[3]), "r"(b[0]), "r"(b[1]));
}

__device__ __forceinline__ void cp_async16(uint32_t saddr, const void* g) {
    asm volatile("cp.async.cg.shared.global [%0], [%1], 16;" :: "r"(saddr), "l"(g));
}

__global__ void prep_kernel(const float* __restrict__ W, const int* __restrict__ a2w)
{
    int i = blockIdx.x * blockDim.x + threadIdx.x;
    if (i < 21 * FDIM * TN) g_wtf32[i] = f2tf32(W[i]);
    if (blockIdx.x == 0 && threadIdx.x < 32) {
        int v = a2w[2 * threadIdx.x + 1];
        unsigned m = __ballot_sync(0xffffffffu, v != 0);
        if (threadIdx.x == 0) g_idx64 = (m == 0u) ? 1 : 0;
    }
}

// ---- 8-rows-in-flight gather, degree known at compile time (int32 indices) ----
template<int DEG>
__device__ __forceinline__ void gather8(
    const float* __restrict__ feat, const int* __restrict__ adj,
    int rs, int re, int segstart, int warp, int lane, uint32_t* As)
{
    const int rbase = warp * 8;
    int base[8];
    bool gd[8];
#pragma unroll
    for (int q = 0; q < 8; q++) {
        int r = rs + rbase + q;
        gd[q] = r < re;
        base[q] = (gd[q] ? (r - segstart) : 0) * DEG;
    }
    float4 s[8];
#pragma unroll
    for (int q = 0; q < 8; q++) s[q] = make_float4(0.f, 0.f, 0.f, 0.f);

#pragma unroll
    for (int j = 0; j < DEG; j++) {
        int n[8];
#pragma unroll
        for (int q = 0; q < 8; q++) n[q] = __ldg(adj + base[q] + j);
        float4 v[8];
#pragma unroll
        for (int q = 0; q < 8; q++)
            v[q] = __ldg(reinterpret_cast<const float4*>(feat + (long long)n[q] * FDIM) + lane);
#pragma unroll
        for (int q = 0; q < 8; q++) {
            s[q].x += v[q].x; s[q].y += v[q].y;
            s[q].z += v[q].z; s[q].w += v[q].w;
        }
    }
#pragma unroll
    for (int q = 0; q < 8; q++) {
        uint4 t;
        if (!gd[q]) s[q] = make_float4(0.f, 0.f, 0.f, 0.f);
        t.x = f2tf32(s[q].x); t.y = f2tf32(s[q].y);
        t.z = f2tf32(s[q].z); t.w = f2tf32(s[q].w);
        *reinterpret_cast<uint4*>(&As[(rbase + q) * AS_S + lane * 4]) = t;
    }
}

// ---- generic fallback (int64 indices, runtime degree) ----
__device__ __noinline__ void gather_generic(
    const float* __restrict__ feat, const long long* __restrict__ adj, int deg,
    int rs, int re, int segstart, int warp, int lane, uint32_t* As)
{
    const int rbase = warp * 8;
    for (int g = 0; g < 8; g += 4) {
        float4 s[4];
        long long base[4];
        bool gd[4];
#pragma unroll
        for (int q = 0; q < 4; q++) {
            int r = rs + rbase + g + q;
            gd[q] = r < re;
            base[q] = (long long)(gd[q] ? (r - segstart) : 0) * deg;
            s[q] = make_float4(0.f, 0.f, 0.f, 0.f);
        }
        for (int j = 0; j < deg; j++) {
#pragma unroll
            for (int q = 0; q < 4; q++) {
                long long nb = __ldg(adj + base[q] + j);
                float4 v = __ldg(reinterpret_cast<const float4*>(feat + nb * FDIM) + lane);
                s[q].x += v.x; s[q].y += v.y; s[q].z += v.z; s[q].w += v.w;
            }
        }
#pragma unroll
        for (int q = 0; q < 4; q++) {
            if (!gd[q]) s[q] = make_float4(0.f, 0.f, 0.f, 0.f);
            uint4 t;
            t.x = f2tf32(s[q].x); t.y = f2tf32(s[q].y);
            t.z = f2tf32(s[q].z); t.w = f2tf32(s[q].w);
            *reinterpret_cast<uint4*>(&As[(rbase + g + q) * AS_S + lane * 4]) = t;
        }
    }
}

__global__ __launch_bounds__(256, 3)
void fused_graphconv_kernel(
    const float* __restrict__ feat,
    const float* __restrict__ b,
    float* __restrict__ out,
    const void* __restrict__ a1,  const void* __restrict__ a2,
    const void* __restrict__ a3,  const void* __restrict__ a4,
    const void* __restrict__ a5,  const void* __restrict__ a6,
    const void* __restrict__ a7,  const void* __restrict__ a8,
    const void* __restrict__ a9,  const void* __restrict__ a10)
{
    extern __shared__ uint32_t smem[];
    uint32_t* As = smem;
    uint32_t* Bs = smem + AS_WORDS;

    const int bt = blockIdx.x;
    int seg = 0;
#pragma unroll
    for (int s = 1; s <= 10; s++)
        if (bt >= d_TCUM[s]) seg = s;

    const int rs = d_OFFS[seg] + (bt - d_TCUM[seg]) * TM;
    const int re = d_OFFS[seg + 1];
    const int segstart = d_OFFS[seg];

    const void* adj = nullptr;
    switch (seg) {
        case 1:  adj = a1;  break;  case 2:  adj = a2;  break;
        case 3:  adj = a3;  break;  case 4:  adj = a4;  break;
        case 5:  adj = a5;  break;  case 6:  adj = a6;  break;
        case 7:  adj = a7;  break;  case 8:  adj = a8;  break;
        case 9:  adj = a9;  break;  case 10: adj = a10; break;
        default: break;
    }
    const int idx64 = g_idx64;

    const int tid  = threadIdx.x;
    const int warp = tid >> 5;
    const int lane = tid & 31;
    const int wm = (warp >> 2) * 32;
    const int wn = (warp & 3) * 32;
    const int lq = lane >> 2;
    const int lr = lane & 3;
    const int bk0 = tid >> 5;
    const int bn4 = (tid & 31) * 4;

    const int mat_rel  = (seg == 0) ? 20 : 2 * (seg - 1);
    const int mat_self = (seg == 0) ? 20 : 2 * seg - 1;
    const int nSteps = (seg == 0) ? 4 : 8;

    // Phase stagger: pseudo-random half of the gather tiles run the cheap
    // self pass first, so co-resident CTAs don't execute memory phases in
    // lockstep. (Pass order is commutative: acc accumulates both GEMMs.)
    const bool selfFirst = (seg != 0) && ((bt * 0x9E3779B9u) >> 31);
    const int matP0 = selfFirst ? mat_self : mat_rel;
    const int matP1 = selfFirst ? mat_rel  : mat_self;

    auto issueB = [&](int mat, int s, int buf) {
        const uint32_t* src = g_wtf32 + (mat * FDIM + s * 32) * TN;
        uint32_t* dst = Bs + buf * BS_WORDS;
#pragma unroll
        for (int kk = 0; kk < 4; kk++) {
            int k = bk0 + kk * 8;
            uint32_t sa = (uint32_t)__cvta_generic_to_shared(dst + k * BS_S + bn4);
            cp_async16(sa, src + k * TN + bn4);
        }
        asm volatile("cp.async.commit_group;" ::: "memory");
    };

    auto loadA_self = [&]() {
        const int rbase = warp * 8;
        float4 v[8];
#pragma unroll
        for (int q = 0; q < 8; q++) {
            int r = rs + rbase + q;
            v[q] = make_float4(0.f, 0.f, 0.f, 0.f);
            if (r < re)
                v[q] = __ldg(reinterpret_cast<const float4*>(feat + (long long)r * FDIM) + lane);
        }
#pragma unroll
        for (int q = 0; q < 8; q++) {
            uint4 t;
            t.x = f2tf32(v[q].x); t.y = f2tf32(v[q].y);
            t.z = f2tf32(v[q].z); t.w = f2tf32(v[q].w);
            *reinterpret_cast<uint4*>(&As[(rbase + q) * AS_S + lane * 4]) = t;
        }
    };

    auto loadA_gather = [&]() {
        if (!idx64) {
            const int* a = (const int*)adj;
            switch (seg) {
                case 1:  gather8<1>(feat, a, rs, re, segstart, warp, lane, As); break;
                case 2:  gather8<2>(feat, a, rs, re, segstart, warp, lane, As); break;
                case 3:  gather8<3>(feat, a, rs, re, segstart, warp, lane, As); break;
                case 4:  gather8<4>(feat, a, rs, re, segstart, warp, lane, As); break;
                case 5:  gather8<5>(feat, a, rs, re, segstart, warp, lane, As); break;
                case 6:  gather8<6>(feat, a, rs, re, segstart, warp, lane, As); break;
                case 7:  gather8<7>(feat, a, rs, re, segstart, warp, lane, As); break;
                case 8:  gather8<8>(feat, a, rs, re, segstart, warp, lane, As); break;
                case 9:  gather8<9>(feat, a, rs, re, segstart, warp, lane, As); break;
                default: gather8<10>(feat, a, rs, re, segstart, warp, lane, As); break;
            }
        } else {
            gather_generic(feat, (const long long*)adj, seg, rs, re, segstart, warp, lane, As);
        }
    };

    // ---- prologue: B(0) in flight during the first A phase ----
    issueB(matP0, 0, 0);
    if (seg > 0) {
        if (selfFirst) loadA_self(); else loadA_gather();
    } else {
        loadA_self();
    }

    float acc[2][4][4];
#pragma unroll
    for (int i = 0; i < 2; i++)
#pragma unroll
        for (int j = 0; j < 4; j++)
#pragma unroll
            for (int k = 0; k < 4; k++) acc[i][j][k] = 0.f;

    for (int t = 0; t < nSteps; t++) {
        if (t == 4) {
            __syncthreads();
            if (selfFirst) loadA_gather(); else loadA_self();
        }
        asm volatile("cp.async.wait_group 0;" ::: "memory");
        __syncthreads();
        if (t + 1 < nSteps) {
            int nt = t + 1;
            issueB(nt < 4 ? matP0 : matP1, nt & 3, nt & 1);
        }
        const uint32_t* Bbuf = Bs + (t & 1) * BS_WORDS;
        const int koA = (t & 3) * 32;
#pragma unroll
        for (int ks = 0; ks < 4; ks++) {
            const int ka = koA + ks * 8;
            const int kb = ks * 8;
            uint32_t af[2][4];
#pragma unroll
            for (int mi = 0; mi < 2; mi++) {
                int r0 = wm + 16 * mi + lq;
                int c0 = ka + lr;
                af[mi][0] = As[r0 * AS_S + c0];
                af[mi][1] = As[(r0 + 8) * AS_S + c0];
                af[mi][2] = As[r0 * AS_S + c0 + 4];
                af[mi][3] = As[(r0 + 8) * AS_S + c0 + 4];
            }
            uint32_t bf[4][2];
#pragma unroll
            for (int nj = 0; nj < 4; nj++) {
                int n0 = wn + 8 * nj + lq;
                bf[nj][0] = Bbuf[(kb + lr) * BS_S + n0];
                bf[nj][1] = Bbuf[(kb + lr + 4) * BS_S + n0];
            }
#pragma unroll
            for (int mi = 0; mi < 2; mi++)
#pragma unroll
                for (int nj = 0; nj < 4; nj++)
                    mma_tf32(acc[mi][nj], af[mi], bf[nj]);
        }
    }

    // ---- bias + relu + store ----
    float2 bv[4];
#pragma unroll
    for (int nj = 0; nj < 4; nj++) {
        int n = wn + 8 * nj + 2 * lr;
        float2 bb;
        if (seg == 0) {
            bb.x = __ldg(b + 20 * TN + n);
            bb.y = __ldg(b + 20 * TN + n + 1);
        } else {
            const float* b0 = b + (2 * (seg - 1)) * TN;
            const float* b1 = b + (2 * seg - 1) * TN;
            bb.x = __ldg(b0 + n) + __ldg(b1 + n);
            bb.y = __ldg(b0 + n + 1) + __ldg(b1 + n + 1);
        }
        bv[nj] = bb;
    }

#pragma unroll
    for (int mi = 0; mi < 2; mi++) {
        int r0 = rs + wm + 16 * mi + lq;
#pragma unroll
        for (int nj = 0; nj < 4; nj++) {
            int col = wn + 8 * nj + 2 * lr;
            const float* c = acc[mi][nj];
            if (r0 < re) {
                float2 o;
                o.x = fmaxf(c[0] + bv[nj].x, 0.f);
                o.y = fmaxf(c[1] + bv[nj].y, 0.f);
                *reinterpret_cast<float2*>(out + (long long)r0 * TN + col) = o;
            }
            if (r0 + 8 < re) {
                float2 o;
                o.x = fmaxf(c[2] + bv[nj].x, 0.f);
                o.y = fmaxf(c[3] + bv[nj].y, 0.f);
                *reinterpret_cast<float2*>(out + (long long)(r0 + 8) * TN + col) = o;
            }
        }
    }
}

extern "C" void kernel_launch(void* const* d_in, const int* in_sizes, int n_in,
                              void* d_out, int out_size)
{
    const float* feat = nullptr;
    const float* W = nullptr;
    const float* b = nullptr;
    const void* adj[11] = {nullptr};

    for (int i = 0; i < n_in; i++) {
        switch (in_sizes[i]) {
            case 64000000: feat = (const float*)d_in[i]; break;
            case 344064:   W    = (const float*)d_in[i]; break;
            case 2688:     b    = (const float*)d_in[i]; break;
            case 100000:   adj[1]  = d_in[i]; break;
            case 300000:   adj[2]  = d_in[i]; break;
            case 450000:   adj[3]  = d_in[i]; break;
            case 320000:   adj[4]  = d_in[i]; break;
            case 25000:    adj[5]  = d_in[i]; break;
            case 12000:    adj[6]  = d_in[i]; break;
            case 7000:     adj[7]  = d_in[i]; break;
            case 8000:     adj[8]  = d_in[i]; break;
            case 4500:     adj[9]  = d_in[i]; break;
            case 5000:     adj[10] = d_in[i]; break;
            default: break;
        }
    }

    static bool attr_set = false;
    if (!attr_set) {
        cudaFuncSetAttribute(fused_graphconv_kernel,
                             cudaFuncAttributeMaxDynamicSharedMemorySize, SMEM_BYTES);
        attr_set = true;
    }

    prep_kernel<<<(21 * FDIM * TN + 255) / 256, 256>>>(W, (const int*)adj[2]);

    fused_graphconv_kernel<<<TOTAL_TILES, 256, SMEM_BYTES>>>(
        feat, b, (float*)d_out,
        adj[1], adj[2], adj[3], adj[4], adj[5],
        adj[6], adj[7], adj[8], adj[9], adj[10]);
}

// round 9
// speedup vs baseline: 1.3503x; 1.3503x over previous
#include <cuda_runtime.h>
#include <cstdint>

#define N_ATOMS 500000
#define FDIM 128
#define TM 64
#define TN 128
#define TOTAL_TILES 7817
#define GRID_CTAS 296

#define AS_S 132
#define BS_S 136
#define AS_WORDS (TM * AS_S)          // 8448 words / stage
#define BS_WORDS (32 * BS_S)          // 4352 words / buffer
#define NSTAGE 2
#define SMEM_BYTES ((NSTAGE * AS_WORDS + 2 * BS_WORDS) * 4)   // 102400

// named barrier ids: FULL0=1, FULL1=2, EMPTY0=3, EMPTY1=4, CONS=5

__device__ __constant__ int d_OFFS[12] =
    {0, 10000, 110000, 260000, 410000, 490000, 495000, 497000, 498000, 499000, 499500, 500000};
__device__ __constant__ int d_TCUM[12] =
    {0, 157, 1720, 4064, 6408, 7658, 7737, 7769, 7785, 7801, 7809, 7817};

__device__ int g_idx64;
__device__ uint32_t g_wtf32[21 * FDIM * TN];

__device__ __forceinline__ uint32_t f2tf32(float x) {
    uint32_t y;
    asm("cvt.rna.tf32.f32 %0, %1;" : "=r"(y) : "f"(x));
    return y;
}

__device__ __forceinline__ void mma_tf32(float* c, const uint32_t* a, const uint32_t* b) {
    asm volatile(
        "mma.sync.aligned.m16n8k8.row.col.f32.tf32.tf32.f32 "
        "{%0,%1,%2,%3}, {%4,%5,%6,%7}, {%8,%9}, {%0,%1,%2,%3};\n"
        : "+f"(c[0]), "+f"(c[1]), "+f"(c[2]), "+f"(c[3])
        : "r"(a[0]), "r"(a[1]), "r"(a[2]), "r"(a[3]), "r"(b[0]), "r"(b[1]));
}

__device__ __forceinline__ void cp_async16(uint32_t saddr, const void* g) {
    asm volatile("cp.async.cg.shared.global [%0], [%1], 16;" :: "r"(saddr), "l"(g));
}

__device__ __forceinline__ void bar_sync(int id, int cnt) {
    asm volatile("bar.sync %0, %1;" :: "r"(id), "r"(cnt) : "memory");
}
__device__ __forceinline__ void bar_arrive(int id, int cnt) {
    asm volatile("bar.arrive %0, %1;" :: "r"(id), "r"(cnt) : "memory");
}

__device__ __forceinline__ int seg_of(int bt) {
    int seg = 0;
#pragma unroll
    for (int s = 1; s <= 10; s++)
        if (bt >= d_TCUM[s]) seg = s;
    return seg;
}

__global__ void prep_kernel(const float* __restrict__ W, const int* __restrict__ a2w)
{
    int i = blockIdx.x * blockDim.x + threadIdx.x;
    if (i < 21 * FDIM * TN) g_wtf32[i] = f2tf32(W[i]);
    if (blockIdx.x == 0 && threadIdx.x < 32) {
        int v = a2w[2 * threadIdx.x + 1];
        unsigned m = __ballot_sync(0xffffffffu, v != 0);
        if (threadIdx.x == 0) g_idx64 = (m == 0u) ? 1 : 0;
    }
}

// ---- gather 8 rows (rbase..rbase+7), compile-time degree, int32 indices ----
template<int DEG>
__device__ __forceinline__ void gather8(
    const float* __restrict__ feat, const int* __restrict__ adj,
    int rs, int re, int segstart, int rbase, int lane, uint32_t* As)
{
    int base[8];
    bool gd[8];
#pragma unroll
    for (int q = 0; q < 8; q++) {
        int r = rs + rbase + q;
        gd[q] = r < re;
        base[q] = (gd[q] ? (r - segstart) : 0) * DEG;
    }
    float4 s[8];
#pragma unroll
    for (int q = 0; q < 8; q++) s[q] = make_float4(0.f, 0.f, 0.f, 0.f);
#pragma unroll
    for (int j = 0; j < DEG; j++) {
        int n[8];
#pragma unroll
        for (int q = 0; q < 8; q++) n[q] = __ldg(adj + base[q] + j);
        float4 v[8];
#pragma unroll
        for (int q = 0; q < 8; q++)
            v[q] = __ldg(reinterpret_cast<const float4*>(feat + (long long)n[q] * FDIM) + lane);
#pragma unroll
        for (int q = 0; q < 8; q++) {
            s[q].x += v[q].x; s[q].y += v[q].y;
            s[q].z += v[q].z; s[q].w += v[q].w;
        }
    }
#pragma unroll
    for (int q = 0; q < 8; q++) {
        if (!gd[q]) s[q] = make_float4(0.f, 0.f, 0.f, 0.f);
        uint4 t;
        t.x = f2tf32(s[q].x); t.y = f2tf32(s[q].y);
        t.z = f2tf32(s[q].z); t.w = f2tf32(s[q].w);
        *reinterpret_cast<uint4*>(&As[(rbase + q) * AS_S + lane * 4]) = t;
    }
}

__device__ __noinline__ void gather_generic(
    const float* __restrict__ feat, const long long* __restrict__ adj, int deg,
    int rs, int re, int segstart, int rbase, int lane, uint32_t* As)
{
    for (int g = 0; g < 8; g += 4) {
        float4 s[4];
        long long base[4];
        bool gd[4];
#pragma unroll
        for (int q = 0; q < 4; q++) {
            int r = rs + rbase + g + q;
            gd[q] = r < re;
            base[q] = (long long)(gd[q] ? (r - segstart) : 0) * deg;
            s[q] = make_float4(0.f, 0.f, 0.f, 0.f);
        }
        for (int j = 0; j < deg; j++) {
#pragma unroll
            for (int q = 0; q < 4; q++) {
                long long nb = __ldg(adj + base[q] + j);
                float4 v = __ldg(reinterpret_cast<const float4*>(feat + nb * FDIM) + lane);
                s[q].x += v.x; s[q].y += v.y; s[q].z += v.z; s[q].w += v.w;
            }
        }
#pragma unroll
        for (int q = 0; q < 4; q++) {
            if (!gd[q]) s[q] = make_float4(0.f, 0.f, 0.f, 0.f);
            uint4 t;
            t.x = f2tf32(s[q].x); t.y = f2tf32(s[q].y);
            t.z = f2tf32(s[q].z); t.w = f2tf32(s[q].w);
            *reinterpret_cast<uint4*>(&As[(rbase + g + q) * AS_S + lane * 4]) = t;
        }
    }
}

__device__ __forceinline__ void selfload8(
    const float* __restrict__ feat, int rs, int re, int rbase, int lane, uint32_t* As)
{
    float4 v[8];
#pragma unroll
    for (int q = 0; q < 8; q++) {
        int r = rs + rbase + q;
        v[q] = make_float4(0.f, 0.f, 0.f, 0.f);
        if (r < re)
            v[q] = __ldg(reinterpret_cast<const float4*>(feat + (long long)r * FDIM) + lane);
    }
#pragma unroll
    for (int q = 0; q < 8; q++) {
        uint4 t;
        t.x = f2tf32(v[q].x); t.y = f2tf32(v[q].y);
        t.z = f2tf32(v[q].z); t.w = f2tf32(v[q].w);
        *reinterpret_cast<uint4*>(&As[(rbase + q) * AS_S + lane * 4]) = t;
    }
}

// -----------------------------------------------------------------------------
// Persistent warp-specialized kernel. Warps 4-7 produce A tiles (gather / self
// load) into a 2-stage ring; warps 0-3 consume (tf32 MMA + epilogue).
// -----------------------------------------------------------------------------
__global__ __launch_bounds__(256, 2)
void fused_ws_kernel(
    const float* __restrict__ feat,
    const float* __restrict__ b,
    float* __restrict__ out,
    const void* __restrict__ a1,  const void* __restrict__ a2,
    const void* __restrict__ a3,  const void* __restrict__ a4,
    const void* __restrict__ a5,  const void* __restrict__ a6,
    const void* __restrict__ a7,  const void* __restrict__ a8,
    const void* __restrict__ a9,  const void* __restrict__ a10)
{
    extern __shared__ uint32_t smem[];
    uint32_t* Astg = smem;                        // NSTAGE x AS_WORDS
    uint32_t* Bs   = smem + NSTAGE * AS_WORDS;    // 2 x BS_WORDS

    const int tid  = threadIdx.x;
    const int warp = tid >> 5;
    const int lane = tid & 31;
    const int idx64 = g_idx64;

    if (warp >= 4) {
        // ======================= PRODUCER =======================
        const int pw = warp - 4;                  // 0..3, each owns 16 rows
        int fill = 0;
        for (int tile = blockIdx.x; tile < TOTAL_TILES; tile += GRID_CTAS) {
            const int seg = seg_of(tile);
            const int rs = d_OFFS[seg] + (tile - d_TCUM[seg]) * TM;
            const int re = d_OFFS[seg + 1];
            const int segstart = d_OFFS[seg];
            const void* adj = nullptr;
            switch (seg) {
                case 1:  adj = a1;  break;  case 2:  adj = a2;  break;
                case 3:  adj = a3;  break;  case 4:  adj = a4;  break;
                case 5:  adj = a5;  break;  case 6:  adj = a6;  break;
                case 7:  adj = a7;  break;  case 8:  adj = a8;  break;
                case 9:  adj = a9;  break;  case 10: adj = a10; break;
                default: break;
            }
            const int npass = (seg == 0) ? 1 : 2;
            for (int p = 0; p < npass; p++) {
                const int s = fill & 1;
                if (fill >= NSTAGE) bar_sync(3 + s, 256);   // wait EMPTY_s
                uint32_t* A = Astg + s * AS_WORDS;
                if (seg > 0 && p == 0) {
                    if (!idx64) {
                        const int* a = (const int*)adj;
                        switch (seg) {
                            case 1:  gather8<1>(feat, a, rs, re, segstart, pw*16,   lane, A);
                                     gather8<1>(feat, a, rs, re, segstart, pw*16+8, lane, A); break;
                            case 2:  gather8<2>(feat, a, rs, re, segstart, pw*16,   lane, A);
                                     gather8<2>(feat, a, rs, re, segstart, pw*16+8, lane, A); break;
                            case 3:  gather8<3>(feat, a, rs, re, segstart, pw*16,   lane, A);
                                     gather8<3>(feat, a, rs, re, segstart, pw*16+8, lane, A); break;
                            case 4:  gather8<4>(feat, a, rs, re, segstart, pw*16,   lane, A);
                                     gather8<4>(feat, a, rs, re, segstart, pw*16+8, lane, A); break;
                            case 5:  gather8<5>(feat, a, rs, re, segstart, pw*16,   lane, A);
                                     gather8<5>(feat, a, rs, re, segstart, pw*16+8, lane, A); break;
                            case 6:  gather8<6>(feat, a, rs, re, segstart, pw*16,   lane, A);
                                     gather8<6>(feat, a, rs, re, segstart, pw*16+8, lane, A); break;
                            case 7:  gather8<7>(feat, a, rs, re, segstart, pw*16,   lane, A);
                                     gather8<7>(feat, a, rs, re, segstart, pw*16+8, lane, A); break;
                            case 8:  gather8<8>(feat, a, rs, re, segstart, pw*16,   lane, A);
                                     gather8<8>(feat, a, rs, re, segstart, pw*16+8, lane, A); break;
                            case 9:  gather8<9>(feat, a, rs, re, segstart, pw*16,   lane, A);
                                     gather8<9>(feat, a, rs, re, segstart, pw*16+8, lane, A); break;
                            default: gather8<10>(feat, a, rs, re, segstart, pw*16,   lane, A);
                                     gather8<10>(feat, a, rs, re, segstart, pw*16+8, lane, A); break;
                        }
                    } else {
                        gather_generic(feat, (const long long*)adj, seg, rs, re, segstart, pw*16,   lane, A);
                        gather_generic(feat, (const long long*)adj, seg, rs, re, segstart, pw*16+8, lane, A);
                    }
                } else {
                    selfload8(feat, rs, re, pw*16,   lane, A);
                    selfload8(feat, rs, re, pw*16+8, lane, A);
                }
                __threadfence_block();
                bar_arrive(1 + s, 256);                      // FULL_s
                fill++;
            }
        }
    } else {
        // ======================= CONSUMER =======================
        const int wm = (warp >> 1) * 32;
        const int wn = (warp & 1) * 64;
        const int lq = lane >> 2;
        const int lr = lane & 3;
        const int bk0 = tid >> 4;           // 0..7 (128 consumer threads)
        const int bn8 = (tid & 15) * 8;     // word col

        // B issue iterator (one chunk = 32k x 128n of one matrix)
        int nt = blockIdx.x;
        int nseg = seg_of(nt);
        int npassN = (nseg == 0) ? 1 : 2;
        int np = 0, nc = 0;

        auto issueNextB = [&](int buf) {
            if (nt < TOTAL_TILES) {
                int mat = (nseg == 0) ? 20 : (np == 0 ? 2 * (nseg - 1) : 2 * nseg - 1);
                const uint32_t* src = g_wtf32 + (mat * FDIM + nc * 32) * TN;
                uint32_t* dst = Bs + buf * BS_WORDS;
#pragma unroll
                for (int kk = 0; kk < 4; kk++) {
                    int k = bk0 + kk * 8;
                    uint32_t sa = (uint32_t)__cvta_generic_to_shared(dst + k * BS_S + bn8);
                    cp_async16(sa,      src + k * TN + bn8);
                    cp_async16(sa + 16, src + k * TN + bn8 + 4);
                }
            }
            asm volatile("cp.async.commit_group;" ::: "memory");
            // advance iterator
            if (++nc == 4) {
                nc = 0;
                if (++np == npassN) {
                    np = 0; nt += GRID_CTAS;
                    if (nt < TOTAL_TILES) {
                        nseg = seg_of(nt);
                        npassN = (nseg == 0) ? 1 : 2;
                    }
                }
            }
        };

        issueNextB(0);          // prologue: first chunk into buf 0
        int ib = 1;             // next issue index (buf = ib&1)
        int bc = 0;             // consumed chunk counter (buf = bc&1)
        int cons = 0;           // consumed A-stage counter

        for (int tile = blockIdx.x; tile < TOTAL_TILES; tile += GRID_CTAS) {
            const int seg = seg_of(tile);
            const int rs = d_OFFS[seg] + (tile - d_TCUM[seg]) * TM;
            const int re = d_OFFS[seg + 1];
            const int npass = (seg == 0) ? 1 : 2;

            float acc[2][8][4];
#pragma unroll
            for (int i = 0; i < 2; i++)
#pragma unroll
                for (int j = 0; j < 8; j++)
#pragma unroll
                    for (int k = 0; k < 4; k++) acc[i][j][k] = 0.f;

            for (int p = 0; p < npass; p++) {
                const int s = cons & 1;
                bar_sync(1 + s, 256);                        // wait FULL_s
                const uint32_t* A = Astg + s * AS_WORDS;
                for (int chunk = 0; chunk < 4; chunk++) {
                    asm volatile("cp.async.wait_group 0;" ::: "memory");
                    bar_sync(5, 128);                        // consumer-only
                    issueNextB(ib & 1); ib++;
                    const uint32_t* Bbuf = Bs + (bc & 1) * BS_WORDS; bc++;
                    const int koA = chunk * 32;
#pragma unroll
                    for (int ks = 0; ks < 4; ks++) {
                        const int ka = koA + ks * 8;
                        const int kb = ks * 8;
                        uint32_t af[2][4];
#pragma unroll
                        for (int mi = 0; mi < 2; mi++) {
                            int r0 = wm + 16 * mi + lq;
                            int c0 = ka + lr;
                            af[mi][0] = A[r0 * AS_S + c0];
                            af[mi][1] = A[(r0 + 8) * AS_S + c0];
                            af[mi][2] = A[r0 * AS_S + c0 + 4];
                            af[mi][3] = A[(r0 + 8) * AS_S + c0 + 4];
                        }
                        uint32_t bf[8][2];
#pragma unroll
                        for (int nj = 0; nj < 8; nj++) {
                            int n0 = wn + 8 * nj + lq;
                            bf[nj][0] = Bbuf[(kb + lr) * BS_S + n0];
                            bf[nj][1] = Bbuf[(kb + lr + 4) * BS_S + n0];
                        }
#pragma unroll
                        for (int mi = 0; mi < 2; mi++)
#pragma unroll
                            for (int nj = 0; nj < 8; nj++)
                                mma_tf32(acc[mi][nj], af[mi], bf[nj]);
                    }
                }
                bar_arrive(3 + s, 256);                      // EMPTY_s
                cons++;
            }

            // ---- epilogue: bias + relu + store ----
            float2 bv[8];
#pragma unroll
            for (int nj = 0; nj < 8; nj++) {
                int n = wn + 8 * nj + 2 * lr;
                float2 bb;
                if (seg == 0) {
                    bb.x = __ldg(b + 20 * TN + n);
                    bb.y = __ldg(b + 20 * TN + n + 1);
                } else {
                    const float* b0 = b + (2 * (seg - 1)) * TN;
                    const float* b1 = b + (2 * seg - 1) * TN;
                    bb.x = __ldg(b0 + n) + __ldg(b1 + n);
                    bb.y = __ldg(b0 + n + 1) + __ldg(b1 + n + 1);
                }
                bv[nj] = bb;
            }
#pragma unroll
            for (int mi = 0; mi < 2; mi++) {
                int r0 = rs + wm + 16 * mi + lq;
#pragma unroll
                for (int nj = 0; nj < 8; nj++) {
                    int col = wn + 8 * nj + 2 * lr;
                    const float* c = acc[mi][nj];
                    if (r0 < re) {
                        float2 o;
                        o.x = fmaxf(c[0] + bv[nj].x, 0.f);
                        o.y = fmaxf(c[1] + bv[nj].y, 0.f);
                        *reinterpret_cast<float2*>(out + (long long)r0 * TN + col) = o;
                    }
                    if (r0 + 8 < re) {
                        float2 o;
                        o.x = fmaxf(c[2] + bv[nj].x, 0.f);
                        o.y = fmaxf(c[3] + bv[nj].y, 0.f);
                        *reinterpret_cast<float2*>(out + (long long)(r0 + 8) * TN + col) = o;
                    }
                }
            }
        }
    }
}

extern "C" void kernel_launch(void* const* d_in, const int* in_sizes, int n_in,
                              void* d_out, int out_size)
{
    const float* feat = nullptr;
    const float* W = nullptr;
    const float* b = nullptr;
    const void* adj[11] = {nullptr};

    for (int i = 0; i < n_in; i++) {
        switch (in_sizes[i]) {
            case 64000000: feat = (const float*)d_in[i]; break;
            case 344064:   W    = (const float*)d_in[i]; break;
            case 2688:     b    = (const float*)d_in[i]; break;
            case 100000:   adj[1]  = d_in[i]; break;
            case 300000:   adj[2]  = d_in[i]; break;
            case 450000:   adj[3]  = d_in[i]; break;
            case 320000:   adj[4]  = d_in[i]; break;
            case 25000:    adj[5]  = d_in[i]; break;
            case 12000:    adj[6]  = d_in[i]; break;
            case 7000:     adj[7]  = d_in[i]; break;
            case 8000:     adj[8]  = d_in[i]; break;
            case 4500:     adj[9]  = d_in[i]; break;
            case 5000:     adj[10] = d_in[i]; break;
            default: break;
        }
    }

    static bool attr_set = false;
    if (!attr_set) {
        cudaFuncSetAttribute(fused_ws_kernel,
                             cudaFuncAttributeMaxDynamicSharedMemorySize, SMEM_BYTES);
        attr_set = true;
    }

    prep_kernel<<<(21 * FDIM * TN + 255) / 256, 256>>>(W, (const int*)adj[2]);

    fused_ws_kernel<<<GRID_CTAS, 256, SMEM_BYTES>>>(
        feat, b, (float*)d_out,
        adj[1], adj[2], adj[3], adj[4], adj[5],
        adj[6], adj[7], adj[8], adj[9], adj[10]);
}